// round 14
// baseline (speedup 1.0000x reference)
#include <cuda_runtime.h>
#include <cuda_bf16.h>
#include <stdint.h>

#define S_LEN 4096
#define HID   2048
#define NH    16
#define QPG   4
#define HD    128
#define GROUP 768
#define TOTAL 3072

// Scratch (device globals; bf16 hi/lo pairs)
__device__ __nv_bfloat16 g_xh[S_LEN * HID],   g_xl[S_LEN * HID];
__device__ __nv_bfloat16 g_wqh[TOTAL * HID],  g_wql[TOTAL * HID];
__device__ __nv_bfloat16 g_wph[HID * HID],    g_wpl[HID * HID];
__device__ __nv_bfloat16 g_qh[S_LEN * TOTAL], g_ql[S_LEN * TOTAL];
__device__ __nv_bfloat16 g_ah[S_LEN * HID],   g_al[S_LEN * HID];

// ---------------- sm_80-baseline PTX helpers ----------------
__device__ __forceinline__ uint32_t smem_u32(const void* p) {
    uint32_t a;
    asm("{ .reg .u64 t; cvta.to.shared.u64 t, %1; cvt.u32.u64 %0, t; }"
        : "=r"(a) : "l"(p));
    return a;
}
__device__ __forceinline__ void mma16816(float* c, const uint32_t* a,
                                         const uint32_t* b) {
    asm("mma.sync.aligned.m16n8k16.row.col.f32.bf16.bf16.f32 "
        "{%0,%1,%2,%3}, {%4,%5,%6,%7}, {%8,%9}, {%0,%1,%2,%3};\n"
        : "+f"(c[0]), "+f"(c[1]), "+f"(c[2]), "+f"(c[3])
        : "r"(a[0]), "r"(a[1]), "r"(a[2]), "r"(a[3]), "r"(b[0]), "r"(b[1]));
}
__device__ __forceinline__ void ldsm4(uint32_t* r, uint32_t a) {
    asm volatile("ldmatrix.sync.aligned.m8n8.x4.shared.b16 {%0,%1,%2,%3}, [%4];"
        : "=r"(r[0]), "=r"(r[1]), "=r"(r[2]), "=r"(r[3]) : "r"(a));
}
__device__ __forceinline__ void ldsm4t(uint32_t* r, uint32_t a) {
    asm volatile("ldmatrix.sync.aligned.m8n8.x4.trans.shared.b16 {%0,%1,%2,%3}, [%4];"
        : "=r"(r[0]), "=r"(r[1]), "=r"(r[2]), "=r"(r[3]) : "r"(a));
}
__device__ __forceinline__ void cp16(uint32_t s, const void* g) {
    asm volatile("cp.async.cg.shared.global [%0], [%1], 16;" :: "r"(s), "l"(g));
}
#define CP_COMMIT() asm volatile("cp.async.commit_group;" ::: "memory")
#define CP_WAIT(n)  asm volatile("cp.async.wait_group %0;" :: "n"(n) : "memory")

__device__ __forceinline__ uint32_t u32bf2(__nv_bfloat162 v) {
    return reinterpret_cast<uint32_t&>(v);
}
__device__ __forceinline__ void split2(float a, float b, uint32_t& hi, uint32_t& lo) {
    __nv_bfloat162 h = __floats2bfloat162_rn(a, b);
    __nv_bfloat162 l = __floats2bfloat162_rn(a - __bfloat162float(h.x),
                                             b - __bfloat162float(h.y));
    hi = u32bf2(h); lo = u32bf2(l);
}

// ---------------- fp32 -> bf16 hi/lo split ----------------
__global__ __launch_bounds__(256) void split_kernel(
    const float* __restrict__ x, __nv_bfloat16* __restrict__ hi,
    __nv_bfloat16* __restrict__ lo, int n4)
{
    int i = blockIdx.x * 256 + threadIdx.x;
    if (i >= n4) return;
    float4 v = ((const float4*)x)[i];
    uint32_t h01, l01, h23, l23;
    split2(v.x, v.y, h01, l01);
    split2(v.z, v.w, h23, l23);
    ((uint2*)hi)[i] = make_uint2(h01, h23);
    ((uint2*)lo)[i] = make_uint2(l01, l23);
}

// ===========================================================================
// bf16x3 tensor-core GEMM: C = (Ah+Al)[M,K] * (Bh+Bl)[N,K]^T
// 128x64 tile, BK=64, 2-stage cp.async, 256 thr (8 warps, warp tile 32x32),
// 2 CTAs/SM co-resident (96KB smem/CTA, launch_bounds(256,2)).
// Stage 48KB: Ahi(16K) | Alo(16K) | Bhi(8K) | Blo(8K); rows 128B, XOR swizzle.
// ===========================================================================
#define G_ALO 16384
#define G_BHI 32768
#define G_BLO 40960
#define G_STG 49152
#define GSMEM (2 * G_STG)

template <int SPLIT>
__global__ __launch_bounds__(256, 2) void gemm_mma(
    const __nv_bfloat16* __restrict__ Ah, const __nv_bfloat16* __restrict__ Al,
    const __nv_bfloat16* __restrict__ Bh, const __nv_bfloat16* __restrict__ Bl,
    float* __restrict__ Cf,
    __nv_bfloat16* __restrict__ Ch, __nv_bfloat16* __restrict__ Cl,
    int M, int N, int K)
{
    extern __shared__ char smc[];
    const uint32_t sb0 = smem_u32(smc);
    const int tid = threadIdx.x;
    const int w = tid >> 5, l = tid & 31;
    const int wr = w >> 1, wc = w & 1;          // warp grid 4x2 -> tile 32x32
    const int g = l >> 2, tig = l & 3;
    const int m0 = blockIdx.y * 128, n0 = (int)blockIdx.x * 64;
    const int NK = K >> 6;

    const int alr = tid >> 1, alc = (tid & 1) * 4;   // A: 128 rows, 4 chunks
    const int blr = tid >> 2, blc = (tid & 3) * 2;   // B: 64 rows, 2 chunks

    auto issue = [&](int kt, int st) {
        uint32_t base = sb0 + st * G_STG;
        const __nv_bfloat16* pA = Ah + (size_t)(m0 + alr) * K + kt * 64;
        const __nv_bfloat16* pB = Bh + (size_t)(n0 + blr) * K + kt * 64;
        size_t dAl = Al - Ah, dBl = Bl - Bh;
        uint32_t ra = base + alr * 128;
        uint32_t rb = base + G_BHI + blr * 128;
#pragma unroll
        for (int j = 0; j < 4; ++j) {
            int c = alc + j;
            uint32_t so = ra + ((c ^ (alr & 7)) << 4);
            cp16(so,         pA + c * 8);
            cp16(so + G_ALO, pA + dAl + c * 8);
        }
#pragma unroll
        for (int j = 0; j < 2; ++j) {
            int c = blc + j;
            uint32_t so = rb + ((c ^ (blr & 7)) << 4);
            cp16(so,                   pB + c * 8);
            cp16(so + (G_BLO - G_BHI), pB + dBl + c * 8);
        }
    };

    float acc[2][4][4];
#pragma unroll
    for (int a = 0; a < 2; ++a)
#pragma unroll
        for (int b = 0; b < 4; ++b)
#pragma unroll
            for (int e = 0; e < 4; ++e) acc[a][b][e] = 0.f;

    issue(0, 0); CP_COMMIT();

    for (int kt = 0; kt < NK; ++kt) {
        if (kt + 1 < NK) { issue(kt + 1, (kt + 1) & 1); CP_COMMIT(); CP_WAIT(1); }
        else { CP_WAIT(0); }
        __syncthreads();
        uint32_t base = sb0 + (kt & 1) * G_STG;
#pragma unroll
        for (int ks = 0; ks < 4; ++ks) {
            uint32_t ah[2][4], al[2][4];
#pragma unroll
            for (int mt = 0; mt < 2; ++mt) {
                int row = wr * 32 + mt * 16 + (l & 15);
                int ch = ks * 2 + (l >> 4);
                uint32_t ad = base + row * 128 + ((ch ^ (row & 7)) << 4);
                ldsm4(ah[mt], ad);
                ldsm4(al[mt], ad + G_ALO);
            }
#pragma unroll
            for (int np = 0; np < 2; ++np) {
                int row = wc * 32 + np * 16 + ((l >> 4) & 1) * 8 + (l & 7);
                int ch = ks * 2 + ((l >> 3) & 1);
                uint32_t bd = base + G_BHI + row * 128 + ((ch ^ (row & 7)) << 4);
                uint32_t bh4[4], bl4[4];
                ldsm4(bh4, bd);
                ldsm4(bl4, bd + (G_BLO - G_BHI));
                // pass-major, accumulator-interleaved
                mma16816(acc[0][2 * np],     ah[0], bh4);
                mma16816(acc[1][2 * np],     ah[1], bh4);
                mma16816(acc[0][2 * np + 1], ah[0], bh4 + 2);
                mma16816(acc[1][2 * np + 1], ah[1], bh4 + 2);
                mma16816(acc[0][2 * np],     ah[0], bl4);
                mma16816(acc[1][2 * np],     ah[1], bl4);
                mma16816(acc[0][2 * np + 1], ah[0], bl4 + 2);
                mma16816(acc[1][2 * np + 1], ah[1], bl4 + 2);
                mma16816(acc[0][2 * np],     al[0], bh4);
                mma16816(acc[1][2 * np],     al[1], bh4);
                mma16816(acc[0][2 * np + 1], al[0], bh4 + 2);
                mma16816(acc[1][2 * np + 1], al[1], bh4 + 2);
            }
        }
        __syncthreads();
    }

#pragma unroll
    for (int mt = 0; mt < 2; ++mt) {
        int r0 = m0 + wr * 32 + mt * 16 + g;
        int r1 = r0 + 8;
#pragma unroll
        for (int nt = 0; nt < 4; ++nt) {
            int c = n0 + wc * 32 + nt * 8 + 2 * tig;
            float* a = acc[mt][nt];
            if (SPLIT) {
                uint32_t h01, l01, h23, l23;
                split2(a[0], a[1], h01, l01);
                split2(a[2], a[3], h23, l23);
                size_t o0 = ((size_t)r0 * N + c) >> 1;
                size_t o1 = ((size_t)r1 * N + c) >> 1;
                ((uint32_t*)Ch)[o0] = h01; ((uint32_t*)Cl)[o0] = l01;
                ((uint32_t*)Ch)[o1] = h23; ((uint32_t*)Cl)[o1] = l23;
            } else {
                *(float2*)(Cf + (size_t)r0 * N + c) = make_float2(a[0], a[1]);
                *(float2*)(Cf + (size_t)r1 * N + c) = make_float2(a[2], a[3]);
            }
        }
    }
}

// ===========================================================================
// Tensor-core flash attention (bf16x3 for BOTH QK^T and PV — P_lo required,
// measured: dropping it costs 50x accuracy).  128-row q-tile, 64-key blocks,
// 256 thr (8 warps x m16). Q fragments register-resident.  UNCHANGED.
// ===========================================================================
#define AQL_OFF 32768
#define ASTG    65536
#define AKL 16384
#define AVH 32768
#define AVL 49152
#define ASMEM (65536 + 2 * ASTG)

__global__ __launch_bounds__(256, 1) void attn_mma(
    const __nv_bfloat16* __restrict__ qkv_h,
    const __nv_bfloat16* __restrict__ qkv_l,
    __nv_bfloat16* __restrict__ o_h, __nv_bfloat16* __restrict__ o_l)
{
    extern __shared__ char smc[];
    const uint32_t sb0 = smem_u32(smc);
    const uint32_t kvb = sb0 + 65536;
    const int tid = threadIdx.x;
    const int w = tid >> 5, l = tid & 31;
    const int g = l >> 2, tig = l & 3;
    const int qb = 31 - (int)blockIdx.x;      // heavy tiles first
    const int h = blockIdx.y;
    const int grp = h >> 2, qh = h & 3;
    const int m0 = qb * 128;
    const int qcol = grp * GROUP + qh * HD;
    const int kcol = grp * GROUP + QPG * HD;
    const int vcol = kcol + HD;
    const int ntmax = 2 * qb + 1;

    // stage Q (hi/lo)
    {
        int lr = tid >> 1, lc = (tid & 1) * 8;
        const __nv_bfloat16* gh = qkv_h + (size_t)(m0 + lr) * TOTAL + qcol;
        size_t dl = qkv_l - qkv_h;
        uint32_t ro = sb0 + lr * 256;
#pragma unroll
        for (int j = 0; j < 8; ++j) {
            int c = lc + j;
            uint32_t so = ro + ((c ^ (lr & 7)) << 4);
            cp16(so, gh + c * 8);
            cp16(so + AQL_OFF, gh + dl + c * 8);
        }
    }
    CP_COMMIT();

    const int klr = tid >> 2, klc = (tid & 3) * 4;
    auto issueKV = [&](int nt, int st) {
        size_t rowg = (size_t)(64 * nt + klr) * TOTAL;
        const __nv_bfloat16* pk = qkv_h + rowg + kcol;
        const __nv_bfloat16* pv = qkv_h + rowg + vcol;
        size_t dl = qkv_l - qkv_h;
        uint32_t ro = kvb + st * ASTG + klr * 256;
#pragma unroll
        for (int j = 0; j < 4; ++j) {
            int c = klc + j;
            uint32_t so = ro + ((c ^ (klr & 7)) << 4);
            cp16(so,       pk + c * 8);
            cp16(so + AKL, pk + dl + c * 8);
            cp16(so + AVH, pv + c * 8);
            cp16(so + AVL, pv + dl + c * 8);
        }
    };
    issueKV(0, 0); CP_COMMIT();

    // Q fragments -> registers (hoisted out of KV loop)
    uint32_t qfh[8][4], qfl[8][4];
    CP_WAIT(1);            // Q group complete (KV0 may still be in flight)
    __syncthreads();
    {
        int qrow = w * 16 + (l & 15);
#pragma unroll
        for (int ks = 0; ks < 8; ++ks) {
            int ch = ks * 2 + (l >> 4);
            uint32_t qa = sb0 + qrow * 256 + ((ch ^ (qrow & 7)) << 4);
            ldsm4(qfh[ks], qa);
            ldsm4(qfl[ks], qa + AQL_OFF);
        }
    }

    float of[16][4];
#pragma unroll
    for (int d = 0; d < 16; ++d)
#pragma unroll
        for (int e = 0; e < 4; ++e) of[d][e] = 0.f;
    float mr0 = -1e30f, mr1 = -1e30f, ls0 = 0.f, ls1 = 0.f;
    const float scl = 0.08838834764831845f;   // 1/sqrt(128)
    const int row0 = m0 + w * 16 + g, row1 = row0 + 8;

    for (int nt = 0; nt <= ntmax; ++nt) {
        if (nt < ntmax) { issueKV(nt + 1, (nt + 1) & 1); CP_COMMIT(); CP_WAIT(1); }
        else { CP_WAIT(0); }
        __syncthreads();
        uint32_t base = kvb + (nt & 1) * ASTG;

        // S = Q K^T (bf16x3), pass-major + acc-interleaved
        float sf[8][4];
#pragma unroll
        for (int n8 = 0; n8 < 8; ++n8)
#pragma unroll
            for (int e = 0; e < 4; ++e) sf[n8][e] = 0.f;
#pragma unroll
        for (int ks = 0; ks < 8; ++ks) {
#pragma unroll
            for (int np = 0; np < 4; ++np) {
                int krow = np * 16 + ((l >> 4) & 1) * 8 + (l & 7);
                int kch = ks * 2 + ((l >> 3) & 1);
                uint32_t ka = base + krow * 256 + ((kch ^ (krow & 7)) << 4);
                uint32_t kh4[4], kl4[4];
                ldsm4(kh4, ka);
                ldsm4(kl4, ka + AKL);
                mma16816(sf[2 * np],     qfh[ks], kh4);
                mma16816(sf[2 * np + 1], qfh[ks], kh4 + 2);
                mma16816(sf[2 * np],     qfh[ks], kl4);
                mma16816(sf[2 * np + 1], qfh[ks], kl4 + 2);
                mma16816(sf[2 * np],     qfl[ks], kh4);
                mma16816(sf[2 * np + 1], qfl[ks], kh4 + 2);
            }
        }

        // scale + causal mask
        if (nt >= 2 * qb) {
#pragma unroll
            for (int n8 = 0; n8 < 8; ++n8) {
                int cb = 64 * nt + n8 * 8 + 2 * tig;
                sf[n8][0] = (cb     <= row0) ? sf[n8][0] * scl : -1e30f;
                sf[n8][1] = (cb + 1 <= row0) ? sf[n8][1] * scl : -1e30f;
                sf[n8][2] = (cb     <= row1) ? sf[n8][2] * scl : -1e30f;
                sf[n8][3] = (cb + 1 <= row1) ? sf[n8][3] * scl : -1e30f;
            }
        } else {
#pragma unroll
            for (int n8 = 0; n8 < 8; ++n8)
#pragma unroll
                for (int e = 0; e < 4; ++e) sf[n8][e] *= scl;
        }

        // online softmax
        float mx0 = -1e30f, mx1 = -1e30f;
#pragma unroll
        for (int n8 = 0; n8 < 8; ++n8) {
            mx0 = fmaxf(mx0, fmaxf(sf[n8][0], sf[n8][1]));
            mx1 = fmaxf(mx1, fmaxf(sf[n8][2], sf[n8][3]));
        }
        mx0 = fmaxf(mx0, __shfl_xor_sync(0xffffffffu, mx0, 1));
        mx0 = fmaxf(mx0, __shfl_xor_sync(0xffffffffu, mx0, 2));
        mx1 = fmaxf(mx1, __shfl_xor_sync(0xffffffffu, mx1, 1));
        mx1 = fmaxf(mx1, __shfl_xor_sync(0xffffffffu, mx1, 2));
        float mn0 = fmaxf(mr0, mx0), mn1 = fmaxf(mr1, mx1);
        float c0 = __expf(mr0 - mn0), c1 = __expf(mr1 - mn1);
        mr0 = mn0; mr1 = mn1;
        float rs0 = 0.f, rs1 = 0.f;
#pragma unroll
        for (int n8 = 0; n8 < 8; ++n8) {
            sf[n8][0] = __expf(sf[n8][0] - mn0);
            sf[n8][1] = __expf(sf[n8][1] - mn0);
            sf[n8][2] = __expf(sf[n8][2] - mn1);
            sf[n8][3] = __expf(sf[n8][3] - mn1);
            rs0 += sf[n8][0] + sf[n8][1];
            rs1 += sf[n8][2] + sf[n8][3];
        }
        rs0 += __shfl_xor_sync(0xffffffffu, rs0, 1);
        rs0 += __shfl_xor_sync(0xffffffffu, rs0, 2);
        rs1 += __shfl_xor_sync(0xffffffffu, rs1, 1);
        rs1 += __shfl_xor_sync(0xffffffffu, rs1, 2);
        ls0 = ls0 * c0 + rs0;
        ls1 = ls1 * c1 + rs1;
#pragma unroll
        for (int d = 0; d < 16; ++d) {
            of[d][0] *= c0; of[d][1] *= c0;
            of[d][2] *= c1; of[d][3] *= c1;
        }

        // O += P V (bf16x3), pass-major + acc-interleaved; V via paired ldsm4t.
#pragma unroll
        for (int kc = 0; kc < 4; ++kc) {
            uint32_t ph[4], pl[4];
#pragma unroll
            for (int hf = 0; hf < 2; ++hf) {
                float* p = sf[2 * kc + hf];
                split2(p[0], p[1], ph[hf * 2],     pl[hf * 2]);
                split2(p[2], p[3], ph[hf * 2 + 1], pl[hf * 2 + 1]);
            }
            int vrow = kc * 16 + (l & 15);
            uint32_t vro = base + AVH + vrow * 256;
#pragma unroll
            for (int dp = 0; dp < 8; ++dp) {
                int dd = dp * 2 + (l >> 4);
                uint32_t va = vro + ((dd ^ (vrow & 7)) << 4);
                uint32_t vh4[4], vl4[4];
                ldsm4t(vh4, va);
                ldsm4t(vl4, va + (AVL - AVH));
                mma16816(of[2 * dp],     ph, vh4);
                mma16816(of[2 * dp + 1], ph, vh4 + 2);
                mma16816(of[2 * dp],     pl, vh4);
                mma16816(of[2 * dp + 1], pl, vh4 + 2);
                mma16816(of[2 * dp],     ph, vl4);
                mma16816(of[2 * dp + 1], ph, vl4 + 2);
            }
        }
        __syncthreads();
    }

    // normalize + split-write O
    float i0 = 1.f / ls0, i1 = 1.f / ls1;
#pragma unroll
    for (int d = 0; d < 16; ++d) {
        int col = h * HD + d * 8 + 2 * tig;
        uint32_t h01, l01, h23, l23;
        split2(of[d][0] * i0, of[d][1] * i0, h01, l01);
        split2(of[d][2] * i1, of[d][3] * i1, h23, l23);
        size_t o0 = ((size_t)row0 * HID + col) >> 1;
        size_t o1 = ((size_t)row1 * HID + col) >> 1;
        ((uint32_t*)o_h)[o0] = h01; ((uint32_t*)o_l)[o0] = l01;
        ((uint32_t*)o_h)[o1] = h23; ((uint32_t*)o_l)[o1] = l23;
    }
}

// ---------------- launch ----------------
extern "C" void kernel_launch(void* const* d_in, const int* in_sizes, int n_in,
                              void* d_out, int out_size)
{
    (void)in_sizes; (void)n_in; (void)out_size;
    const float* x     = (const float*)d_in[0];
    const float* w_qkv = (const float*)d_in[1];
    const float* w_prj = (const float*)d_in[2];
    float* out = (float*)d_out;

    __nv_bfloat16 *xh, *xl, *wqh, *wql, *wph, *wpl, *qh, *ql, *ah, *al;
    cudaGetSymbolAddress((void**)&xh, g_xh);   cudaGetSymbolAddress((void**)&xl, g_xl);
    cudaGetSymbolAddress((void**)&wqh, g_wqh); cudaGetSymbolAddress((void**)&wql, g_wql);
    cudaGetSymbolAddress((void**)&wph, g_wph); cudaGetSymbolAddress((void**)&wpl, g_wpl);
    cudaGetSymbolAddress((void**)&qh, g_qh);   cudaGetSymbolAddress((void**)&ql, g_ql);
    cudaGetSymbolAddress((void**)&ah, g_ah);   cudaGetSymbolAddress((void**)&al, g_al);

    cudaFuncSetAttribute(gemm_mma<1>, cudaFuncAttributeMaxDynamicSharedMemorySize, GSMEM);
    cudaFuncSetAttribute(gemm_mma<0>, cudaFuncAttributeMaxDynamicSharedMemorySize, GSMEM);
    cudaFuncSetAttribute(attn_mma,    cudaFuncAttributeMaxDynamicSharedMemorySize, ASMEM);

    split_kernel<<<(S_LEN * HID / 4 + 255) / 256, 256>>>(x, xh, xl, S_LEN * HID / 4);
    split_kernel<<<(TOTAL * HID / 4 + 255) / 256, 256>>>(w_qkv, wqh, wql, TOTAL * HID / 4);
    split_kernel<<<(HID * HID / 4 + 255) / 256, 256>>>(w_prj, wph, wpl, HID * HID / 4);

    // 1) QKV projection -> split bf16 qkv  (128x64 tiles, 2 CTAs/SM)
    gemm_mma<1><<<dim3(TOTAL / 64, S_LEN / 128), 256, GSMEM>>>(
        xh, xl, wqh, wql, nullptr, qh, ql, S_LEN, TOTAL, HID);

    // 2) causal GQA flash attention -> split bf16
    attn_mma<<<dim3(32, NH), 256, ASMEM>>>(qh, ql, ah, al);

    // 3) output projection -> fp32 out
    gemm_mma<0><<<dim3(HID / 64, S_LEN / 128), 256, GSMEM>>>(
        ah, al, wph, wpl, out, nullptr, nullptr, S_LEN, HID, HID);
}

// round 16
// speedup vs baseline: 1.5397x; 1.5397x over previous
#include <cuda_runtime.h>
#include <cuda_fp16.h>
#include <stdint.h>

#define S_LEN 4096
#define HID   2048
#define NH    16
#define QPG   4
#define HD    128
#define GROUP 768
#define TOTAL 3072

// Scratch (device globals; fp16 hi/lo pairs — lo unused for quantized operands)
__device__ __half g_xh[S_LEN * HID],   g_xl[S_LEN * HID];
__device__ __half g_wqh[TOTAL * HID],  g_wql[TOTAL * HID];
__device__ __half g_wph[HID * HID],    g_wpl[HID * HID];
__device__ __half g_qh[S_LEN * TOTAL], g_ql[S_LEN * TOTAL];
__device__ __half g_ah[S_LEN * HID],   g_al[S_LEN * HID];

// ---------------- sm_80-baseline PTX helpers ----------------
__device__ __forceinline__ uint32_t smem_u32(const void* p) {
    uint32_t a;
    asm("{ .reg .u64 t; cvta.to.shared.u64 t, %1; cvt.u32.u64 %0, t; }"
        : "=r"(a) : "l"(p));
    return a;
}
__device__ __forceinline__ void mma16816(float* c, const uint32_t* a,
                                         const uint32_t* b) {
    asm("mma.sync.aligned.m16n8k16.row.col.f32.f16.f16.f32 "
        "{%0,%1,%2,%3}, {%4,%5,%6,%7}, {%8,%9}, {%0,%1,%2,%3};\n"
        : "+f"(c[0]), "+f"(c[1]), "+f"(c[2]), "+f"(c[3])
        : "r"(a[0]), "r"(a[1]), "r"(a[2]), "r"(a[3]), "r"(b[0]), "r"(b[1]));
}
__device__ __forceinline__ void ldsm4(uint32_t* r, uint32_t a) {
    asm volatile("ldmatrix.sync.aligned.m8n8.x4.shared.b16 {%0,%1,%2,%3}, [%4];"
        : "=r"(r[0]), "=r"(r[1]), "=r"(r[2]), "=r"(r[3]) : "r"(a));
}
__device__ __forceinline__ void ldsm4t(uint32_t* r, uint32_t a) {
    asm volatile("ldmatrix.sync.aligned.m8n8.x4.trans.shared.b16 {%0,%1,%2,%3}, [%4];"
        : "=r"(r[0]), "=r"(r[1]), "=r"(r[2]), "=r"(r[3]) : "r"(a));
}
__device__ __forceinline__ void cp16(uint32_t s, const void* g) {
    asm volatile("cp.async.cg.shared.global [%0], [%1], 16;" :: "r"(s), "l"(g));
}
#define CP_COMMIT() asm volatile("cp.async.commit_group;" ::: "memory")
#define CP_WAIT(n)  asm volatile("cp.async.wait_group %0;" :: "n"(n) : "memory")

__device__ __forceinline__ uint32_t u32h2(__half2 v) {
    return reinterpret_cast<uint32_t&>(v);
}
// fp16 hi/lo split of two fp32 values
__device__ __forceinline__ void split2(float a, float b, uint32_t& hi, uint32_t& lo) {
    __half2 h = __floats2half2_rn(a, b);
    __half2 l = __floats2half2_rn(a - __half2float(__low2half(h)),
                                  b - __half2float(__high2half(h)));
    hi = u32h2(h); lo = u32h2(l);
}

// ---------------- fp32 -> fp16 hi/lo split ----------------
__global__ __launch_bounds__(256) void split_kernel(
    const float* __restrict__ x, __half* __restrict__ hi,
    __half* __restrict__ lo, int n4)
{
    int i = blockIdx.x * 256 + threadIdx.x;
    if (i >= n4) return;
    float4 v = ((const float4*)x)[i];
    uint32_t h01, l01, h23, l23;
    split2(v.x, v.y, h01, l01);
    split2(v.z, v.w, h23, l23);
    ((uint2*)hi)[i] = make_uint2(h01, h23);
    ((uint2*)lo)[i] = make_uint2(l01, l23);
}

// ===========================================================================
// fp16x2 tensor-core GEMM: C = (Ah+Al)[M,K] * Bh[N,K]^T   (B fp16-quantized)
// 128x256 tile, BK=64, 2-stage cp.async, 512 thr (16 warps), warp tile 32x64.
// Stage 64KB: Ahi(16K) | Alo(16K) | Bhi(32K); rows 128B, XOR swizzle.
// ===========================================================================
#define G_ALO 16384
#define G_BHI 32768
#define G_STG 65536
#define GSMEM (2 * G_STG)

template <int SPLIT>
__global__ __launch_bounds__(512, 1) void gemm_mma(
    const __half* __restrict__ Ah, const __half* __restrict__ Al,
    const __half* __restrict__ Bh,
    float* __restrict__ Cf,
    __half* __restrict__ Ch, __half* __restrict__ Cl,
    int M, int N, int K)
{
    extern __shared__ char smc[];
    const uint32_t sb0 = smem_u32(smc);
    const int tid = threadIdx.x;
    const int w = tid >> 5, l = tid & 31;
    const int wr = w >> 2, wc = w & 3;          // warp grid 4x4 -> tile 32x64
    const int g = l >> 2, tig = l & 3;
    const int m0 = blockIdx.y * 128, n0 = (int)blockIdx.x * 256;
    const int NK = K >> 6;

    const int alr = tid >> 2, alc = (tid & 3) * 2;   // A: 128 rows, 2 chunks
    const int blr = tid >> 1, blc = (tid & 1) * 4;   // B: 256 rows, 4 chunks

    auto issue = [&](int kt, int st) {
        uint32_t base = sb0 + st * G_STG;
        const __half* pA = Ah + (size_t)(m0 + alr) * K + kt * 64;
        const __half* pB = Bh + (size_t)(n0 + blr) * K + kt * 64;
        size_t dAl = Al - Ah;
        uint32_t ra = base + alr * 128;
        uint32_t rb = base + G_BHI + blr * 128;
#pragma unroll
        for (int j = 0; j < 2; ++j) {
            int c = alc + j;
            uint32_t so = ra + ((c ^ (alr & 7)) << 4);
            cp16(so,         pA + c * 8);
            cp16(so + G_ALO, pA + dAl + c * 8);
        }
#pragma unroll
        for (int j = 0; j < 4; ++j) {
            int c = blc + j;
            uint32_t so = rb + ((c ^ (blr & 7)) << 4);
            cp16(so, pB + c * 8);
        }
    };

    float acc[2][8][4];
#pragma unroll
    for (int a = 0; a < 2; ++a)
#pragma unroll
        for (int b = 0; b < 8; ++b)
#pragma unroll
            for (int e = 0; e < 4; ++e) acc[a][b][e] = 0.f;

    issue(0, 0); CP_COMMIT();

    for (int kt = 0; kt < NK; ++kt) {
        if (kt + 1 < NK) { issue(kt + 1, (kt + 1) & 1); CP_COMMIT(); CP_WAIT(1); }
        else { CP_WAIT(0); }
        __syncthreads();
        uint32_t base = sb0 + (kt & 1) * G_STG;
#pragma unroll
        for (int ks = 0; ks < 4; ++ks) {
            uint32_t ah[2][4], al[2][4];
#pragma unroll
            for (int mt = 0; mt < 2; ++mt) {
                int row = wr * 32 + mt * 16 + (l & 15);
                int ch = ks * 2 + (l >> 4);
                uint32_t ad = base + row * 128 + ((ch ^ (row & 7)) << 4);
                ldsm4(ah[mt], ad);
                ldsm4(al[mt], ad + G_ALO);
            }
#pragma unroll
            for (int np = 0; np < 4; ++np) {
                int row = wc * 64 + np * 16 + ((l >> 4) & 1) * 8 + (l & 7);
                int ch = ks * 2 + ((l >> 3) & 1);
                uint32_t bd = base + G_BHI + row * 128 + ((ch ^ (row & 7)) << 4);
                uint32_t bh4[4];
                ldsm4(bh4, bd);
                mma16816(acc[0][2 * np],     ah[0], bh4);
                mma16816(acc[1][2 * np],     ah[1], bh4);
                mma16816(acc[0][2 * np + 1], ah[0], bh4 + 2);
                mma16816(acc[1][2 * np + 1], ah[1], bh4 + 2);
                mma16816(acc[0][2 * np],     al[0], bh4);
                mma16816(acc[1][2 * np],     al[1], bh4);
                mma16816(acc[0][2 * np + 1], al[0], bh4 + 2);
                mma16816(acc[1][2 * np + 1], al[1], bh4 + 2);
            }
        }
        __syncthreads();
    }

#pragma unroll
    for (int mt = 0; mt < 2; ++mt) {
        int r0 = m0 + wr * 32 + mt * 16 + g;
        int r1 = r0 + 8;
#pragma unroll
        for (int nt = 0; nt < 8; ++nt) {
            int c = n0 + wc * 64 + nt * 8 + 2 * tig;
            float* a = acc[mt][nt];
            if (SPLIT) {
                uint32_t h01, l01, h23, l23;
                split2(a[0], a[1], h01, l01);
                split2(a[2], a[3], h23, l23);
                size_t o0 = ((size_t)r0 * N + c) >> 1;
                size_t o1 = ((size_t)r1 * N + c) >> 1;
                ((uint32_t*)Ch)[o0] = h01; ((uint32_t*)Cl)[o0] = l01;
                ((uint32_t*)Ch)[o1] = h23; ((uint32_t*)Cl)[o1] = l23;
            } else {
                *(float2*)(Cf + (size_t)r0 * N + c) = make_float2(a[0], a[1]);
                *(float2*)(Cf + (size_t)r1 * N + c) = make_float2(a[2], a[3]);
            }
        }
    }
}

// ===========================================================================
// fp16x2 flash attention: S = (Qh+Ql)*Kh^T, O = (Ph+Pl)*Vh.
// K and V fp16-quantized (single term); Q and P exact (hi+lo).
// 128-row q-tile, 64-key blocks, 256 thr (8 warps x m16).
// Smem: Qhi|Qlo (64KB) + 2 KV stages (32KB each: Khi 16K | Vhi 16K).
// ===========================================================================
#define AQL_OFF 32768
#define ASTG    32768
#define AVH 16384
#define ASMEM (65536 + 2 * ASTG)

__global__ __launch_bounds__(256, 1) void attn_mma(
    const __half* __restrict__ qkv_h,
    const __half* __restrict__ qkv_l,
    __half* __restrict__ o_h, __half* __restrict__ o_l)
{
    extern __shared__ char smc[];
    const uint32_t sb0 = smem_u32(smc);
    const uint32_t kvb = sb0 + 65536;
    const int tid = threadIdx.x;
    const int w = tid >> 5, l = tid & 31;
    const int g = l >> 2, tig = l & 3;
    const int qb = 31 - (int)blockIdx.x;      // heavy tiles first
    const int h = blockIdx.y;
    const int grp = h >> 2, qh = h & 3;
    const int m0 = qb * 128;
    const int qcol = grp * GROUP + qh * HD;
    const int kcol = grp * GROUP + QPG * HD;
    const int vcol = kcol + HD;
    const int ntmax = 2 * qb + 1;

    // stage Q (hi/lo)
    {
        int lr = tid >> 1, lc = (tid & 1) * 8;
        const __half* gh = qkv_h + (size_t)(m0 + lr) * TOTAL + qcol;
        size_t dl = qkv_l - qkv_h;
        uint32_t ro = sb0 + lr * 256;
#pragma unroll
        for (int j = 0; j < 8; ++j) {
            int c = lc + j;
            uint32_t so = ro + ((c ^ (lr & 7)) << 4);
            cp16(so, gh + c * 8);
            cp16(so + AQL_OFF, gh + dl + c * 8);
        }
    }
    CP_COMMIT();

    const int klr = tid >> 2, klc = (tid & 3) * 4;
    auto issueKV = [&](int nt, int st) {
        size_t rowg = (size_t)(64 * nt + klr) * TOTAL;
        const __half* pk = qkv_h + rowg + kcol;
        const __half* pv = qkv_h + rowg + vcol;
        uint32_t ro = kvb + st * ASTG + klr * 256;
#pragma unroll
        for (int j = 0; j < 4; ++j) {
            int c = klc + j;
            uint32_t so = ro + ((c ^ (klr & 7)) << 4);
            cp16(so,       pk + c * 8);
            cp16(so + AVH, pv + c * 8);
        }
    };
    issueKV(0, 0); CP_COMMIT();

    // Q fragments -> registers
    uint32_t qfh[8][4], qfl[8][4];
    CP_WAIT(1);
    __syncthreads();
    {
        int qrow = w * 16 + (l & 15);
#pragma unroll
        for (int ks = 0; ks < 8; ++ks) {
            int ch = ks * 2 + (l >> 4);
            uint32_t qa = sb0 + qrow * 256 + ((ch ^ (qrow & 7)) << 4);
            ldsm4(qfh[ks], qa);
            ldsm4(qfl[ks], qa + AQL_OFF);
        }
    }

    float of[16][4];
#pragma unroll
    for (int d = 0; d < 16; ++d)
#pragma unroll
        for (int e = 0; e < 4; ++e) of[d][e] = 0.f;
    float mr0 = -1e30f, mr1 = -1e30f, ls0 = 0.f, ls1 = 0.f;
    const float scl = 0.08838834764831845f;   // 1/sqrt(128)
    const int row0 = m0 + w * 16 + g, row1 = row0 + 8;

    for (int nt = 0; nt <= ntmax; ++nt) {
        if (nt < ntmax) { issueKV(nt + 1, (nt + 1) & 1); CP_COMMIT(); CP_WAIT(1); }
        else { CP_WAIT(0); }
        __syncthreads();
        uint32_t base = kvb + (nt & 1) * ASTG;

        // S = (Qh+Ql) Kh^T
        float sf[8][4];
#pragma unroll
        for (int n8 = 0; n8 < 8; ++n8)
#pragma unroll
            for (int e = 0; e < 4; ++e) sf[n8][e] = 0.f;
#pragma unroll
        for (int ks = 0; ks < 8; ++ks) {
#pragma unroll
            for (int np = 0; np < 4; ++np) {
                int krow = np * 16 + ((l >> 4) & 1) * 8 + (l & 7);
                int kch = ks * 2 + ((l >> 3) & 1);
                uint32_t ka = base + krow * 256 + ((kch ^ (krow & 7)) << 4);
                uint32_t kh4[4];
                ldsm4(kh4, ka);
                mma16816(sf[2 * np],     qfh[ks], kh4);
                mma16816(sf[2 * np + 1], qfh[ks], kh4 + 2);
                mma16816(sf[2 * np],     qfl[ks], kh4);
                mma16816(sf[2 * np + 1], qfl[ks], kh4 + 2);
            }
        }

        // scale + causal mask
        if (nt >= 2 * qb) {
#pragma unroll
            for (int n8 = 0; n8 < 8; ++n8) {
                int cb = 64 * nt + n8 * 8 + 2 * tig;
                sf[n8][0] = (cb     <= row0) ? sf[n8][0] * scl : -1e30f;
                sf[n8][1] = (cb + 1 <= row0) ? sf[n8][1] * scl : -1e30f;
                sf[n8][2] = (cb     <= row1) ? sf[n8][2] * scl : -1e30f;
                sf[n8][3] = (cb + 1 <= row1) ? sf[n8][3] * scl : -1e30f;
            }
        } else {
#pragma unroll
            for (int n8 = 0; n8 < 8; ++n8)
#pragma unroll
                for (int e = 0; e < 4; ++e) sf[n8][e] *= scl;
        }

        // online softmax
        float mx0 = -1e30f, mx1 = -1e30f;
#pragma unroll
        for (int n8 = 0; n8 < 8; ++n8) {
            mx0 = fmaxf(mx0, fmaxf(sf[n8][0], sf[n8][1]));
            mx1 = fmaxf(mx1, fmaxf(sf[n8][2], sf[n8][3]));
        }
        mx0 = fmaxf(mx0, __shfl_xor_sync(0xffffffffu, mx0, 1));
        mx0 = fmaxf(mx0, __shfl_xor_sync(0xffffffffu, mx0, 2));
        mx1 = fmaxf(mx1, __shfl_xor_sync(0xffffffffu, mx1, 1));
        mx1 = fmaxf(mx1, __shfl_xor_sync(0xffffffffu, mx1, 2));
        float mn0 = fmaxf(mr0, mx0), mn1 = fmaxf(mr1, mx1);
        float c0 = __expf(mr0 - mn0), c1 = __expf(mr1 - mn1);
        mr0 = mn0; mr1 = mn1;
        float rs0 = 0.f, rs1 = 0.f;
#pragma unroll
        for (int n8 = 0; n8 < 8; ++n8) {
            sf[n8][0] = __expf(sf[n8][0] - mn0);
            sf[n8][1] = __expf(sf[n8][1] - mn0);
            sf[n8][2] = __expf(sf[n8][2] - mn1);
            sf[n8][3] = __expf(sf[n8][3] - mn1);
            rs0 += sf[n8][0] + sf[n8][1];
            rs1 += sf[n8][2] + sf[n8][3];
        }
        rs0 += __shfl_xor_sync(0xffffffffu, rs0, 1);
        rs0 += __shfl_xor_sync(0xffffffffu, rs0, 2);
        rs1 += __shfl_xor_sync(0xffffffffu, rs1, 1);
        rs1 += __shfl_xor_sync(0xffffffffu, rs1, 2);
        ls0 = ls0 * c0 + rs0;
        ls1 = ls1 * c1 + rs1;
#pragma unroll
        for (int d = 0; d < 16; ++d) {
            of[d][0] *= c0; of[d][1] *= c0;
            of[d][2] *= c1; of[d][3] *= c1;
        }

        // O += (Ph+Pl) Vh  (V fp16-quantized; P exact)
#pragma unroll
        for (int kc = 0; kc < 4; ++kc) {
            uint32_t ph[4], pl[4];
#pragma unroll
            for (int hf = 0; hf < 2; ++hf) {
                float* p = sf[2 * kc + hf];
                split2(p[0], p[1], ph[hf * 2],     pl[hf * 2]);
                split2(p[2], p[3], ph[hf * 2 + 1], pl[hf * 2 + 1]);
            }
            int vrow = kc * 16 + (l & 15);
            uint32_t vro = base + AVH + vrow * 256;
#pragma unroll
            for (int dp = 0; dp < 8; ++dp) {
                int dd = dp * 2 + (l >> 4);
                uint32_t va = vro + ((dd ^ (vrow & 7)) << 4);
                uint32_t vh4[4];
                ldsm4t(vh4, va);
                mma16816(of[2 * dp],     ph, vh4);
                mma16816(of[2 * dp + 1], ph, vh4 + 2);
                mma16816(of[2 * dp],     pl, vh4);
                mma16816(of[2 * dp + 1], pl, vh4 + 2);
            }
        }
        __syncthreads();
    }

    // normalize + split-write O (fp16 hi/lo for GEMM2)
    float i0 = 1.f / ls0, i1 = 1.f / ls1;
#pragma unroll
    for (int d = 0; d < 16; ++d) {
        int col = h * HD + d * 8 + 2 * tig;
        uint32_t h01, l01, h23, l23;
        split2(of[d][0] * i0, of[d][1] * i0, h01, l01);
        split2(of[d][2] * i1, of[d][3] * i1, h23, l23);
        size_t o0 = ((size_t)row0 * HID + col) >> 1;
        size_t o1 = ((size_t)row1 * HID + col) >> 1;
        ((uint32_t*)o_h)[o0] = h01; ((uint32_t*)o_l)[o0] = l01;
        ((uint32_t*)o_h)[o1] = h23; ((uint32_t*)o_l)[o1] = l23;
    }
}

// ---------------- launch ----------------
extern "C" void kernel_launch(void* const* d_in, const int* in_sizes, int n_in,
                              void* d_out, int out_size)
{
    (void)in_sizes; (void)n_in; (void)out_size;
    const float* x     = (const float*)d_in[0];
    const float* w_qkv = (const float*)d_in[1];
    const float* w_prj = (const float*)d_in[2];
    float* out = (float*)d_out;

    __half *xh, *xl, *wqh, *wql, *wph, *wpl, *qh, *ql, *ah, *al;
    cudaGetSymbolAddress((void**)&xh, g_xh);   cudaGetSymbolAddress((void**)&xl, g_xl);
    cudaGetSymbolAddress((void**)&wqh, g_wqh); cudaGetSymbolAddress((void**)&wql, g_wql);
    cudaGetSymbolAddress((void**)&wph, g_wph); cudaGetSymbolAddress((void**)&wpl, g_wpl);
    cudaGetSymbolAddress((void**)&qh, g_qh);   cudaGetSymbolAddress((void**)&ql, g_ql);
    cudaGetSymbolAddress((void**)&ah, g_ah);   cudaGetSymbolAddress((void**)&al, g_al);

    cudaFuncSetAttribute(gemm_mma<1>, cudaFuncAttributeMaxDynamicSharedMemorySize, GSMEM);
    cudaFuncSetAttribute(gemm_mma<0>, cudaFuncAttributeMaxDynamicSharedMemorySize, GSMEM);
    cudaFuncSetAttribute(attn_mma,    cudaFuncAttributeMaxDynamicSharedMemorySize, ASMEM);

    split_kernel<<<(S_LEN * HID / 4 + 255) / 256, 256>>>(x, xh, xl, S_LEN * HID / 4);
    split_kernel<<<(TOTAL * HID / 4 + 255) / 256, 256>>>(w_qkv, wqh, wql, TOTAL * HID / 4);
    split_kernel<<<(HID * HID / 4 + 255) / 256, 256>>>(w_prj, wph, wpl, HID * HID / 4);

    // 1) QKV projection -> split fp16 qkv  (A=x exact, B=W_qkv fp16)
    gemm_mma<1><<<dim3(TOTAL / 256, S_LEN / 128), 512, GSMEM>>>(
        xh, xl, wqh, nullptr, qh, ql, S_LEN, TOTAL, HID);

    // 2) causal GQA flash attention -> split fp16
    attn_mma<<<dim3(32, NH), 256, ASMEM>>>(qh, ql, ah, al);

    // 3) output projection -> fp32 out  (A=attn exact, B=W_proj fp16)
    gemm_mma<0><<<dim3(HID / 256, S_LEN / 128), 512, GSMEM>>>(
        ah, al, wph, out, nullptr, nullptr, S_LEN, HID, HID);
}